// round 13
// baseline (speedup 1.0000x reference)
#include <cuda_runtime.h>
#include <math.h>

// LSTM T=512, B=128, D_in=H=512.  FULLY FUSED single persistent kernel:
//   gates(t) = x_t @ Wx + h_{t-1} @ Wh + b, accumulated in one register set.
// 128 free-running CTAs x 256 thr. CTA(cx,ry): gate cols [cx*64,+64) =
// units [16cx,+16), batch rows [ry*32,+32). Split-K: group kg = tid>>7 owns
// k in [kg*256,+256) for BOTH the x-part and the h-part.
// Per step: (1) x-GEMM (LDG-fed from X + L2-resident repacked Wx) — no
// dependency, hides producer latency; (2) poll per-producer flags, fill h
// into smem; (3) h-GEMM (LDS-fed, Wh slice smem-resident); (4) cross-group
// partial exchange; (5) fused LSTM epilogue (c in regs), packed h store;
// (6) release-store flag.
// init_kernel: repack Wx gate-interleaved (col = j*4+gate), reset flags.

#define T_STEPS 512
#define BATCH   128
#define HID     512
#define DIN     512
#define NG      2048
#define BH      (BATCH * HID)

__device__ float g_Wx[DIN * NG];                    // 4 MB, gate-interleaved
__device__ unsigned int g_flag[4096];               // flag[(ry*32+cx)*32]

typedef unsigned long long ull;
union F4U { float4 f; ull u[2]; float s[4]; };

__device__ __forceinline__ void ffma2(ull& d, ull a, ull b) {
    asm("fma.rn.f32x2 %0, %1, %2, %0;" : "+l"(d) : "l"(a), "l"(b));
}
__device__ __forceinline__ ull dup2(float x) {
    ull r; asm("mov.b64 %0, {%1, %1};" : "=l"(r) : "f"(x)); return r;
}
__device__ __forceinline__ void unpk(ull v, float& lo, float& hi) {
    asm("mov.b64 {%0, %1}, %2;" : "=f"(lo), "=f"(hi) : "l"(v));
}
__device__ __forceinline__ float sigm(float x) {
    return __fdividef(1.0f, 1.0f + __expf(-x));
}
__device__ __forceinline__ float tanh_(float x) {
    return __fdividef(2.0f, 1.0f + __expf(-2.0f * x)) - 1.0f;
}
__device__ __forceinline__ unsigned ld_acquire(const unsigned* p) {
    unsigned v;
    asm volatile("ld.acquire.gpu.global.u32 %0, [%1];"
                 : "=r"(v) : "l"(p) : "memory");
    return v;
}
__device__ __forceinline__ void st_release(unsigned* p, unsigned v) {
    asm volatile("st.release.gpu.global.u32 [%0], %1;"
                 :: "l"(p), "r"(v) : "memory");
}
__device__ __forceinline__ void barx(int id, int cnt) {
    asm volatile("bar.sync %0, %1;" :: "r"(id), "r"(cnt) : "memory");
}

// ---------------------------------------------------------------------------
__global__ __launch_bounds__(256) void init_kernel(
    const float* __restrict__ Wf, const float* __restrict__ Wi,
    const float* __restrict__ Wg, const float* __restrict__ Wo)
{
    int idx = blockIdx.x * 256 + threadIdx.x;
    if (idx < 128) g_flag[idx * 32] = 0;
    if (idx < DIN * NG) {
        int k   = idx / NG;
        int col = idx % NG;
        int j   = col >> 2;
        int g   = col & 3;
        const float* W = (g == 0) ? Wf : (g == 1) ? Wi : (g == 2) ? Wg : Wo;
        g_Wx[idx] = W[(size_t)k * HID + j];        // rows [0, 512) = x weights
    }
}

// ---------------------------------------------------------------------------
// Persistent fused kernel. Grid (32 cx, 4 ry), 256 threads.
// Thread map (within 128-thread group): tx = tg&7 -> 8 gate cols = 2 units,
// ty = tg>>3 -> row pair. Microtile 2 rows x 8 cols (4 col-pairs), acc[2][4].
// Epilogue: group kg owns local row kg; other row's partial exchanged via smem.
// ---------------------------------------------------------------------------
#define HSTRIDE 516
#define WS_FLOATS   (512 * 64)
#define HS_FLOATS   (32 * HSTRIDE)
#define CB_FLOAT4S  (2 * 128 * 2)
#define SMEM_PERSIST ((WS_FLOATS + HS_FLOATS) * 4 + CB_FLOAT4S * 16)

__global__ __launch_bounds__(256, 1) void lstm_fused(
    float* __restrict__ out, int write_final,
    const float* __restrict__ X,
    const float* __restrict__ Wf, const float* __restrict__ Wi,
    const float* __restrict__ Wg, const float* __restrict__ Wo,
    const float* __restrict__ bfp, const float* __restrict__ bip,
    const float* __restrict__ bgp, const float* __restrict__ bop)
{
    extern __shared__ float smem[];
    float*  Ws = smem;                       // [512][64] gate-interleaved Wh
    float*  Hs = smem + WS_FLOATS;           // [32][HSTRIDE] h staging
    float4* Cb = (float4*)(smem + WS_FLOATS + HS_FLOATS);  // [2][128][2]

    const int tid   = threadIdx.x;
    const int lane  = tid & 31;
    const int tg    = tid & 127;
    const int kg    = tid >> 7;              // 0,1: k half
    const int tx    = tg & 7;                // col octet
    const int ty    = tg >> 3;               // row pair 0..15
    const int cl    = tx << 3;               // local col 0..56
    const int cx    = blockIdx.x;
    const int col0  = cx * 64;
    const int ry    = blockIdx.y;
    const int row_base = ry * 32;
    const int u0    = (col0 + cl) >> 2;      // first owned hidden unit
    const int r0    = row_base + ty * 2;
    const int ro    = r0 + kg;               // owned epilogue row
    const int kbase = kg * 256;

    unsigned* fme = &g_flag[(ry * 32 + cx) * 32];
    const unsigned* fwatch = &g_flag[(ry * 32 + kg * 16 + (lane & 15)) * 32];

    // Preload gate-interleaved Wh slice into smem (once, gathered).
    {
        const int jbase = col0 >> 2;
        #pragma unroll
        for (int g = 0; g < 4; g++) {
            const float* Wp = (g == 0) ? Wf : (g == 1) ? Wi : (g == 2) ? Wg : Wo;
            for (int p = 0; p < 32; p++) {
                int idx = tid + p * 256;
                int k = idx >> 4, u = idx & 15;
                Ws[k * 64 + u * 4 + g] = Wp[(size_t)(DIN + k) * HID + jbase + u];
            }
        }
    }

    // Bias for the 8 owned gate cols (2 units).
    float b8[8];
    b8[0] = bfp[u0];     b8[1] = bip[u0];     b8[2] = bgp[u0];     b8[3] = bop[u0];
    b8[4] = bfp[u0 + 1]; b8[5] = bip[u0 + 1]; b8[6] = bgp[u0 + 1]; b8[7] = bop[u0 + 1];
    __syncthreads();

    float creg[2]  = {0.f, 0.f};             // c state: 2 units at owned row
    float hlast[2] = {0.f, 0.f};

    const int frow = tg >> 2;                // fill: row 0..31
    const int fc4  = (tg & 3) << 2;          // fill: float offset in 16-chunk

    const float* hr0 = &Hs[(ty * 2) * HSTRIDE + kbase];
    const float* hr1 = hr0 + HSTRIDE;
    const float* wsp = Ws + (size_t)kbase * 64 + cl;
    const float* wxp = g_Wx + (size_t)kbase * NG / 32 * 2;   // = kbase*64 (slice below)

    // Wx slice base for this CTA's cols (row stride NG in the packed array!).
    const float* wxbase = g_Wx + (size_t)kbase * NG + col0 + cl;

    for (int t = 0; t < T_STEPS; t++) {
        ull acc[2][4];
        #pragma unroll
        for (int i = 0; i < 2; i++)
            #pragma unroll
            for (int c = 0; c < 4; c++) acc[i][c] = 0ull;

        // ---- Phase 1: x-GEMM over own k-half (no dependency) ----
        {
            const float* xp0 = X + ((size_t)t * BATCH + r0) * DIN + kbase;
            const float* xp1 = xp0 + DIN;
            #pragma unroll 4
            for (int g4 = 0; g4 < 64; g4++) {
                F4U xa0, xa1;
                xa0.f = __ldg((const float4*)(xp0 + g4 * 4));
                xa1.f = __ldg((const float4*)(xp1 + g4 * 4));
                #pragma unroll
                for (int kk = 0; kk < 4; kk++) {
                    F4U w0, w1;
                    w0.f = __ldg((const float4*)(wxbase + (size_t)(g4 * 4 + kk) * NG));
                    w1.f = __ldg((const float4*)(wxbase + (size_t)(g4 * 4 + kk) * NG + 4));
                    ull d0 = dup2(xa0.s[kk]);
                    ull d1 = dup2(xa1.s[kk]);
                    ffma2(acc[0][0], d0, w0.u[0]); ffma2(acc[0][1], d0, w0.u[1]);
                    ffma2(acc[0][2], d0, w1.u[0]); ffma2(acc[0][3], d0, w1.u[1]);
                    ffma2(acc[1][0], d1, w0.u[0]); ffma2(acc[1][1], d1, w0.u[1]);
                    ffma2(acc[1][2], d1, w1.u[0]); ffma2(acc[1][3], d1, w1.u[1]);
                }
            }
        }

        // ---- Phase 2+3: wait for h_{t-1}, fill, h-GEMM ----
        if (t > 0) {
            while (ld_acquire(fwatch) < (unsigned)t) { }
            barx(1 + kg, 128);               // happens-before for all 16 flags

            const float* hp = out + (size_t)(t - 1) * BH + (size_t)(row_base + frow) * HID;
            #pragma unroll
            for (int cc = 0; cc < 16; cc++) {
                int kc = (kg * 16 + cc) * 16 + fc4;
                float4 v = __ldcg((const float4*)(hp + kc));
                *(float4*)&Hs[frow * HSTRIDE + kc] = v;
            }
            barx(1 + kg, 128);

            // h-GEMM, register double-buffered.
            F4U ha0, ha1, hb0, hb1;
            F4U wb[4], wbn[4];
            ha0.f = *(const float4*)(hr0);
            ha1.f = *(const float4*)(hr1);
            #pragma unroll
            for (int kk = 0; kk < 4; kk++) {
                wb[kk].u[0] = *(const ull*)(wsp + kk * 64);
                wb[kk].u[1] = *(const ull*)(wsp + kk * 64 + 2);
            }
            // wb holds 8 cols? need 2 float4 per k. Restructure: wb[kk] pairs.
            // (loaded as two 64-bit halves of the first float4; second float4 below)
            F4U wc[4], wcn[4];
            #pragma unroll
            for (int kk = 0; kk < 4; kk++) wc[kk].f = *(const float4*)(wsp + kk * 64 + 4);
            #pragma unroll
            for (int kk = 0; kk < 4; kk++) wb[kk].f = *(const float4*)(wsp + kk * 64);

            #pragma unroll 2
            for (int g4 = 0; g4 < 64; g4++) {
                if (g4 < 63) {
                    int kn = (g4 + 1) * 4;
                    hb0.f = *(const float4*)(hr0 + kn);
                    hb1.f = *(const float4*)(hr1 + kn);
                    #pragma unroll
                    for (int kk = 0; kk < 4; kk++) {
                        wbn[kk].f = *(const float4*)(wsp + (kn + kk) * 64);
                        wcn[kk].f = *(const float4*)(wsp + (kn + kk) * 64 + 4);
                    }
                }
                #pragma unroll
                for (int kk = 0; kk < 4; kk++) {
                    ull d0 = dup2(ha0.s[kk]);
                    ull d1 = dup2(ha1.s[kk]);
                    ffma2(acc[0][0], d0, wb[kk].u[0]); ffma2(acc[0][1], d0, wb[kk].u[1]);
                    ffma2(acc[0][2], d0, wc[kk].u[0]); ffma2(acc[0][3], d0, wc[kk].u[1]);
                    ffma2(acc[1][0], d1, wb[kk].u[0]); ffma2(acc[1][1], d1, wb[kk].u[1]);
                    ffma2(acc[1][2], d1, wc[kk].u[0]); ffma2(acc[1][3], d1, wc[kk].u[1]);
                }
                ha0 = hb0; ha1 = hb1;
                #pragma unroll
                for (int kk = 0; kk < 4; kk++) { wb[kk] = wbn[kk]; wc[kk] = wcn[kk]; }
            }
        }

        // ---- Phase 4: cross-group partial exchange (always: x-part is split) ----
        __syncthreads();
        {
            int other = 1 - kg;              // local row the other group owns
            Cb[(kg * 128 + tg) * 2 + 0] = ((F4U*)&acc[other][0])->f;
            F4U p2; p2.u[0] = acc[other][2]; p2.u[1] = acc[other][3];
            F4U p1; p1.u[0] = acc[other][0]; p1.u[1] = acc[other][1];
            Cb[(kg * 128 + tg) * 2 + 0] = p1.f;
            Cb[(kg * 128 + tg) * 2 + 1] = p2.f;
        }
        __syncthreads();

        // ---- Phase 5: fused LSTM epilogue, own row only ----
        {
            F4U q1, q2;
            q1.f = Cb[((1 - kg) * 128 + tg) * 2 + 0];
            q2.f = Cb[((1 - kg) * 128 + tg) * 2 + 1];
            float o[8];
            unpk(acc[kg][0], o[0], o[1]); unpk(acc[kg][1], o[2], o[3]);
            unpk(acc[kg][2], o[4], o[5]); unpk(acc[kg][3], o[6], o[7]);
            o[0] += q1.s[0] + b8[0]; o[1] += q1.s[1] + b8[1];
            o[2] += q1.s[2] + b8[2]; o[3] += q1.s[3] + b8[3];
            o[4] += q2.s[0] + b8[4]; o[5] += q2.s[1] + b8[5];
            o[6] += q2.s[2] + b8[6]; o[7] += q2.s[3] + b8[7];

            float h2[2];
            #pragma unroll
            for (int u = 0; u < 2; u++) {
                float f  = sigm(o[u * 4 + 0]);
                float iv = sigm(o[u * 4 + 1]);
                float g  = tanh_(o[u * 4 + 2]);
                float oo = sigm(o[u * 4 + 3]);
                float cn = f * creg[u] + iv * g;
                creg[u]  = cn;
                h2[u]    = oo * tanh_(cn);
                hlast[u] = h2[u];
            }
            float2 hv = make_float2(h2[0], h2[1]);
            __stcg((float2*)(out + (size_t)t * BH + (size_t)ro * HID + u0), hv);
        }

        // ---- Phase 6: publish h_t ----
        if (t < T_STEPS - 1) {
            __syncthreads();
            if (tid == 0) st_release(fme, (unsigned)(t + 1));
        }
    }

    if (write_final) {
        size_t base = (size_t)T_STEPS * BH;
        out[base + (size_t)ro * HID + u0]          = hlast[0];
        out[base + (size_t)ro * HID + u0 + 1]      = hlast[1];
        out[base + BH + (size_t)ro * HID + u0]     = creg[0];
        out[base + BH + (size_t)ro * HID + u0 + 1] = creg[1];
    }
}

// ---------------------------------------------------------------------------
extern "C" void kernel_launch(void* const* d_in, const int* in_sizes, int n_in,
                              void* d_out, int out_size)
{
    const float* x  = (const float*)d_in[0];
    const float* Wf = (const float*)d_in[1];
    const float* bf = (const float*)d_in[2];
    const float* Wi = (const float*)d_in[3];
    const float* bi = (const float*)d_in[4];
    const float* Wg = (const float*)d_in[5];
    const float* bg = (const float*)d_in[6];
    const float* Wo = (const float*)d_in[7];
    const float* bo = (const float*)d_in[8];
    float* out = (float*)d_out;

    static int attr_set = 0;
    if (!attr_set) {
        cudaFuncSetAttribute(lstm_fused,
                             cudaFuncAttributeMaxDynamicSharedMemorySize,
                             SMEM_PERSIST);
        attr_set = 1;
    }

    init_kernel<<<(DIN * NG + 255) / 256, 256>>>(Wf, Wi, Wg, Wo);

    long long need = (long long)T_STEPS * BH + 2LL * BH;
    int wf = ((long long)out_size >= need) ? 1 : 0;
    lstm_fused<<<dim3(32, 4), 256, SMEM_PERSIST>>>(
        out, wf, x, Wf, Wi, Wg, Wo, bf, bi, bg, bo);
}

// round 15
// speedup vs baseline: 1.4923x; 1.4923x over previous
#include <cuda_runtime.h>
#include <math.h>

// LSTM T=512, B=128, D_in=H=512.  Two kernels:
//  sgemm_x:      Gx[65536 x 2048] = X @ Wx + bias (gate-interleaved, FFMA2).
//                Bias lives ONLY here (R14 bug: it was also added in persist).
//  lstm_persist: 128 free-running CTAs x 512 thr, 512 steps, no global barrier.
//                Split-K FOUR groups of 128 threads (k-quarters of 128);
//                4 warps/SMSP for issue eligibility; single-buffered operand
//                loads; 1 output cell (row, unit) per thread in the epilogue.

#define T_STEPS 512
#define BATCH   128
#define HID     512
#define DIN     512
#define NG      2048
#define M_ALL   (T_STEPS * BATCH)
#define BH      (BATCH * HID)

__device__ float g_Gx[(size_t)M_ALL * NG];          // 512 MB scratch
__device__ unsigned int g_flag[4096];               // flag[(ry*32+cx)*32]

typedef unsigned long long ull;
union F4U { float4 f; ull u[2]; float s[4]; };

__device__ __forceinline__ void ffma2(ull& d, ull a, ull b) {
    asm("fma.rn.f32x2 %0, %1, %2, %0;" : "+l"(d) : "l"(a), "l"(b));
}
__device__ __forceinline__ ull dup2(float x) {
    ull r; asm("mov.b64 %0, {%1, %1};" : "=l"(r) : "f"(x)); return r;
}
__device__ __forceinline__ void unpk(ull v, float& lo, float& hi) {
    asm("mov.b64 {%0, %1}, %2;" : "=f"(lo), "=f"(hi) : "l"(v));
}
__device__ __forceinline__ float sigm(float x) {
    return __fdividef(1.0f, 1.0f + __expf(-x));
}
__device__ __forceinline__ float tanh_(float x) {
    return __fdividef(2.0f, 1.0f + __expf(-2.0f * x)) - 1.0f;
}
__device__ __forceinline__ unsigned ld_acquire(const unsigned* p) {
    unsigned v;
    asm volatile("ld.acquire.gpu.global.u32 %0, [%1];"
                 : "=r"(v) : "l"(p) : "memory");
    return v;
}
__device__ __forceinline__ void st_release(unsigned* p, unsigned v) {
    asm volatile("st.release.gpu.global.u32 [%0], %1;"
                 :: "l"(p), "r"(v) : "memory");
}
__device__ __forceinline__ void barx(int id, int cnt) {
    asm volatile("bar.sync %0, %1;" :: "r"(id), "r"(cnt) : "memory");
}

// ---------------------------------------------------------------------------
// Phase 1: Gx = X @ Wx + bias.  128x128 tile, BK=16, 256 thr, 8x8 microtile,
// FFMA2, register double-buffering, gate-interleaved B gather. (R11-proven.)
// ---------------------------------------------------------------------------
#define BM 128
#define BN 128
#define BK 16

__global__ __launch_bounds__(256) void sgemm_x(
    const float* __restrict__ X,
    const float* __restrict__ Wf, const float* __restrict__ Wi,
    const float* __restrict__ Wg, const float* __restrict__ Wo,
    const float* __restrict__ bfp, const float* __restrict__ bip,
    const float* __restrict__ bgp, const float* __restrict__ bop)
{
    __shared__ float As[BK][BM + 4];
    __shared__ float Bs[BK][BN];

    const int tid  = threadIdx.x;
    const int tx   = tid & 15;
    const int ty   = tid >> 4;
    const int row0 = blockIdx.y * BM;
    const int col0 = blockIdx.x * BN;

    if (blockIdx.x == 0 && blockIdx.y == 0 && tid < 128)
        g_flag[tid * 32] = 0;

    const int ar0 = tid >> 2, ak0 = (tid & 3) << 2;
    const int ar1 = (tid + 256) >> 2, ak1 = ((tid + 256) & 3) << 2;
    const int br0 = tid >> 5, br1 = (tid + 256) >> 5;
    const int jj  = (col0 >> 2) + (tid & 31);
    const int bc  = (tid & 31) << 2;

    float4 pa0, pa1;
    float  pb0[4], pb1[4];

    pa0 = *(const float4*)(X + (size_t)(row0 + ar0) * DIN + ak0);
    pa1 = *(const float4*)(X + (size_t)(row0 + ar1) * DIN + ak1);
    {
        size_t o0 = (size_t)br0 * HID + jj, o1 = (size_t)br1 * HID + jj;
        pb0[0] = Wf[o0]; pb0[1] = Wi[o0]; pb0[2] = Wg[o0]; pb0[3] = Wo[o0];
        pb1[0] = Wf[o1]; pb1[1] = Wi[o1]; pb1[2] = Wg[o1]; pb1[3] = Wo[o1];
    }
    As[ak0 + 0][ar0] = pa0.x; As[ak0 + 1][ar0] = pa0.y;
    As[ak0 + 2][ar0] = pa0.z; As[ak0 + 3][ar0] = pa0.w;
    As[ak1 + 0][ar1] = pa1.x; As[ak1 + 1][ar1] = pa1.y;
    As[ak1 + 2][ar1] = pa1.z; As[ak1 + 3][ar1] = pa1.w;
    Bs[br0][bc + 0] = pb0[0]; Bs[br0][bc + 1] = pb0[1];
    Bs[br0][bc + 2] = pb0[2]; Bs[br0][bc + 3] = pb0[3];
    Bs[br1][bc + 0] = pb1[0]; Bs[br1][bc + 1] = pb1[1];
    Bs[br1][bc + 2] = pb1[2]; Bs[br1][bc + 3] = pb1[3];
    __syncthreads();

    ull acc[8][4];
    #pragma unroll
    for (int i = 0; i < 8; i++)
        #pragma unroll
        for (int j = 0; j < 4; j++) acc[i][j] = 0ull;

    for (int k0 = 0; k0 < DIN; k0 += BK) {
        const bool more = (k0 + BK) < DIN;
        if (more) {
            int kn = k0 + BK;
            pa0 = *(const float4*)(X + (size_t)(row0 + ar0) * DIN + kn + ak0);
            pa1 = *(const float4*)(X + (size_t)(row0 + ar1) * DIN + kn + ak1);
            size_t o0 = (size_t)(kn + br0) * HID + jj;
            size_t o1 = (size_t)(kn + br1) * HID + jj;
            pb0[0] = Wf[o0]; pb0[1] = Wi[o0]; pb0[2] = Wg[o0]; pb0[3] = Wo[o0];
            pb1[0] = Wf[o1]; pb1[1] = Wi[o1]; pb1[2] = Wg[o1]; pb1[3] = Wo[o1];
        }

        #pragma unroll
        for (int k = 0; k < BK; k++) {
            F4U aA, aB, bA, bB;
            aA.f = *(float4*)&As[k][ty * 8];
            aB.f = *(float4*)&As[k][ty * 8 + 4];
            bA.f = *(float4*)&Bs[k][tx * 8];
            bB.f = *(float4*)&Bs[k][tx * 8 + 4];
            ull ad[8];
            #pragma unroll
            for (int i = 0; i < 4; i++) { ad[i] = dup2(aA.s[i]); ad[4 + i] = dup2(aB.s[i]); }
            #pragma unroll
            for (int i = 0; i < 8; i++) {
                ffma2(acc[i][0], ad[i], bA.u[0]);
                ffma2(acc[i][1], ad[i], bA.u[1]);
                ffma2(acc[i][2], ad[i], bB.u[0]);
                ffma2(acc[i][3], ad[i], bB.u[1]);
            }
        }
        __syncthreads();
        if (more) {
            As[ak0 + 0][ar0] = pa0.x; As[ak0 + 1][ar0] = pa0.y;
            As[ak0 + 2][ar0] = pa0.z; As[ak0 + 3][ar0] = pa0.w;
            As[ak1 + 0][ar1] = pa1.x; As[ak1 + 1][ar1] = pa1.y;
            As[ak1 + 2][ar1] = pa1.z; As[ak1 + 3][ar1] = pa1.w;
            Bs[br0][bc + 0] = pb0[0]; Bs[br0][bc + 1] = pb0[1];
            Bs[br0][bc + 2] = pb0[2]; Bs[br0][bc + 3] = pb0[3];
            Bs[br1][bc + 0] = pb1[0]; Bs[br1][bc + 1] = pb1[1];
            Bs[br1][bc + 2] = pb1[2]; Bs[br1][bc + 3] = pb1[3];
            __syncthreads();
        }
    }

    const int ju0 = (col0 + tx * 8) >> 2;
    float b8[8];
    b8[0] = bfp[ju0];     b8[1] = bip[ju0];     b8[2] = bgp[ju0];     b8[3] = bop[ju0];
    b8[4] = bfp[ju0 + 1]; b8[5] = bip[ju0 + 1]; b8[6] = bgp[ju0 + 1]; b8[7] = bop[ju0 + 1];

    #pragma unroll
    for (int i = 0; i < 8; i++) {
        int r = row0 + ty * 8 + i;
        int c = col0 + tx * 8;
        float o[8];
        unpk(acc[i][0], o[0], o[1]);
        unpk(acc[i][1], o[2], o[3]);
        unpk(acc[i][2], o[4], o[5]);
        unpk(acc[i][3], o[6], o[7]);
        float4 v0 = make_float4(o[0] + b8[0], o[1] + b8[1], o[2] + b8[2], o[3] + b8[3]);
        float4 v1 = make_float4(o[4] + b8[4], o[5] + b8[5], o[6] + b8[6], o[7] + b8[7]);
        __stcs((float4*)(g_Gx + (size_t)r * NG + c),     v0);
        __stcs((float4*)(g_Gx + (size_t)r * NG + c + 4), v1);
    }
}

// ---------------------------------------------------------------------------
// Phase 2: persistent free-running kernel. Grid (32 cx, 4 ry) = 128 CTAs,
// 512 threads. CTA(cx,ry): gate cols [cx*64,+64) = units [16cx,+16),
// rows [ry*32,+32). Split-K: group q = tid>>7 (128 threads) owns k-quarter
// [q*128,+128). Microtile 2 rows x 8 gate-cols x 128 k, single-buffered.
// Epilogue: thread (q,tg) owns cell row = 2*(tg>>3) + (q&1),
// unit_local = 2*(tg&7) + (q>>1); partials via 32KB combine buffer.
// Bias is ALREADY inside Gx — do not add it here.
// ---------------------------------------------------------------------------
#define HSTRIDE 516
#define WS_FLOATS (512 * 64)
#define HS_FLOATS (32 * HSTRIDE)
#define CB_OFF    (WS_FLOATS + HS_FLOATS)
#define SMEM_PERSIST ((WS_FLOATS + HS_FLOATS + 4 * 128 * 4 * 4) * 4)

__global__ __launch_bounds__(512, 1) void lstm_persist(
    float* __restrict__ out, int write_final,
    const float* __restrict__ Wf, const float* __restrict__ Wi,
    const float* __restrict__ Wg, const float* __restrict__ Wo)
{
    extern __shared__ float smem[];
    float*  Ws = smem;                  // [512][64] gate-interleaved Wh
    float*  Hs = smem + WS_FLOATS;      // [32][HSTRIDE] h staging
    float4* Cb = (float4*)(smem + CB_OFF);  // [4 grp][128 tg][2 row][2 unit]

    const int tid   = threadIdx.x;
    const int lane  = tid & 31;
    const int tg    = tid & 127;
    const int q     = tid >> 7;              // k-quarter group 0..3
    const int tx    = tg & 7;                // col octet
    const int ty    = tg >> 3;               // row pair 0..15
    const int cl    = tx << 3;               // local gate col 0..56
    const int cx    = blockIdx.x;
    const int col0  = cx * 64;
    const int ry    = blockIdx.y;
    const int row_base = ry * 32;
    const int kbase = q * 128;

    // Owned epilogue cell.
    const int rl_o  = ty * 2 + (q & 1);      // local row 0..31
    const int ul_o  = tx * 2 + (q >> 1);     // local unit 0..15
    const int row_o = row_base + rl_o;
    const int u_o   = (col0 >> 2) + ul_o;    // global hidden unit

    unsigned* fme = &g_flag[(ry * 32 + cx) * 32];
    const unsigned* fwatch = &g_flag[(ry * 32 + q * 8 + (lane & 7)) * 32];

    // Preload gate-interleaved Wh slice into smem (once, gathered).
    {
        const int jbase = col0 >> 2;
        #pragma unroll
        for (int g = 0; g < 4; g++) {
            const float* Wp = (g == 0) ? Wf : (g == 1) ? Wi : (g == 2) ? Wg : Wo;
            for (int p = 0; p < 16; p++) {
                int idx = tid + p * 512;
                int k = idx >> 4, u = idx & 15;
                Ws[k * 64 + u * 4 + g] = Wp[(size_t)(DIN + k) * HID + jbase + u];
            }
        }
    }
    __syncthreads();

    float creg  = 0.f;
    float hlast = 0.f;

    const int frow = tg >> 2;                // fill: row 0..31
    const int fc4  = (tg & 3) << 2;          // fill: float offset in 16-chunk

    const float* hr0 = &Hs[(ty * 2) * HSTRIDE + kbase];
    const float* hr1 = hr0 + HSTRIDE;
    const float* wsp = Ws + (size_t)kbase * 64 + cl;

    // Combine-read source indices (partial for owned cell from each group).
    const int tg_src = (rl_o >> 1) * 8 + (ul_o >> 1);
    const int ri     = rl_o & 1;
    const int hi     = ul_o & 1;

    for (int t = 0; t < T_STEPS; t++) {
        // Prefetch owned cell's Gx quad (includes bias).
        float4 gx = __ldcs((const float4*)(
            g_Gx + ((size_t)t * BATCH + row_o) * NG + col0 + ul_o * 4));

        ull acc[2][4];
        #pragma unroll
        for (int i = 0; i < 2; i++)
            #pragma unroll
            for (int c = 0; c < 4; c++) acc[i][c] = 0ull;

        if (t > 0) {
            // Poll the 8 producers covering this k-quarter.
            while (ld_acquire(fwatch) < (unsigned)t) { }
            barx(1 + q, 128);

            // Fill own k-quarter of Hs: 32 rows x 128 floats.
            const float* hp = out + (size_t)(t - 1) * BH
                              + (size_t)(row_base + frow) * HID + kbase;
            #pragma unroll
            for (int cc = 0; cc < 8; cc++) {
                int kc = cc * 16 + fc4;
                float4 v = __ldcg((const float4*)(hp + kc));
                *(float4*)&Hs[frow * HSTRIDE + kbase + kc] = v;
            }
            barx(1 + q, 128);

            // h-GEMM over own 128-k quarter (single-buffered; 4 warps/SMSP
            // provide the latency hiding).
            #pragma unroll 4
            for (int g4 = 0; g4 < 32; g4++) {
                F4U ha0, ha1;
                ha0.f = *(const float4*)(hr0 + g4 * 4);
                ha1.f = *(const float4*)(hr1 + g4 * 4);
                #pragma unroll
                for (int kk = 0; kk < 4; kk++) {
                    F4U wb, wc;
                    wb.f = *(const float4*)(wsp + (g4 * 4 + kk) * 64);
                    wc.f = *(const float4*)(wsp + (g4 * 4 + kk) * 64 + 4);
                    ull d0 = dup2(ha0.s[kk]);
                    ull d1 = dup2(ha1.s[kk]);
                    ffma2(acc[0][0], d0, wb.u[0]); ffma2(acc[0][1], d0, wb.u[1]);
                    ffma2(acc[0][2], d0, wc.u[0]); ffma2(acc[0][3], d0, wc.u[1]);
                    ffma2(acc[1][0], d1, wb.u[0]); ffma2(acc[1][1], d1, wb.u[1]);
                    ffma2(acc[1][2], d1, wc.u[0]); ffma2(acc[1][3], d1, wc.u[1]);
                }
            }
        }

        // Combine: every thread publishes its 2x8 partial (4 float4s).
        __syncthreads();
        {
            float4* dst = &Cb[((q * 128 + tg) * 2) * 2];
            #pragma unroll
            for (int r = 0; r < 2; r++) {
                F4U p0; p0.u[0] = acc[r][0]; p0.u[1] = acc[r][1];
                F4U p1; p1.u[0] = acc[r][2]; p1.u[1] = acc[r][3];
                dst[r * 2 + 0] = p0.f;
                dst[r * 2 + 1] = p1.f;
            }
        }
        __syncthreads();

        // Fused LSTM epilogue: 1 owned (row, unit) cell. NO bias here.
        {
            float pf = gx.x, pi = gx.y, pg = gx.z, po = gx.w;
            #pragma unroll
            for (int s = 0; s < 4; s++) {
                F4U p; p.f = Cb[((s * 128 + tg_src) * 2 + ri) * 2 + hi];
                pf += p.s[0]; pi += p.s[1]; pg += p.s[2]; po += p.s[3];
            }
            float f  = sigm(pf);
            float iv = sigm(pi);
            float g  = tanh_(pg);
            float oo = sigm(po);
            float cn = f * creg + iv * g;
            creg  = cn;
            hlast = oo * tanh_(cn);
            __stcg(&out[(size_t)t * BH + (size_t)row_o * HID + u_o], hlast);
        }

        // Publish h_t.
        if (t < T_STEPS - 1) {
            __syncthreads();
            if (tid == 0) st_release(fme, (unsigned)(t + 1));
        }
    }

    if (write_final) {
        size_t base = (size_t)T_STEPS * BH;
        out[base + (size_t)row_o * HID + u_o]      = hlast;
        out[base + BH + (size_t)row_o * HID + u_o] = creg;
    }
}

// ---------------------------------------------------------------------------
extern "C" void kernel_launch(void* const* d_in, const int* in_sizes, int n_in,
                              void* d_out, int out_size)
{
    const float* x  = (const float*)d_in[0];
    const float* Wf = (const float*)d_in[1];
    const float* bf = (const float*)d_in[2];
    const float* Wi = (const float*)d_in[3];
    const float* bi = (const float*)d_in[4];
    const float* Wg = (const float*)d_in[5];
    const float* bg = (const float*)d_in[6];
    const float* Wo = (const float*)d_in[7];
    const float* bo = (const float*)d_in[8];
    float* out = (float*)d_out;

    static int attr_set = 0;
    if (!attr_set) {
        cudaFuncSetAttribute(lstm_persist,
                             cudaFuncAttributeMaxDynamicSharedMemorySize,
                             SMEM_PERSIST);
        attr_set = 1;
    }

    dim3 g1(NG / BN, M_ALL / BM);
    sgemm_x<<<g1, 256>>>(x, Wf, Wi, Wg, Wo, bf, bi, bg, bo);

    long long need = (long long)T_STEPS * BH + 2LL * BH;
    int wf = ((long long)out_size >= need) ? 1 : 0;
    lstm_persist<<<dim3(32, 4), 512, SMEM_PERSIST>>>(out, wf, Wf, Wi, Wg, Wo);
}

// round 17
// speedup vs baseline: 2.9893x; 2.0031x over previous
#include <cuda_runtime.h>
#include <cuda_bf16.h>
#include <math.h>

// LSTM T=512, B=128, D_in=H=512.  Three kernels:
//  preconvert: X -> Xhi/Xlo bf16, Wx -> gate-interleaved Bhi/Blo bf16, bias, flags.
//  tensor_gx:  Gx = X @ Wx + bias via mma.sync.m16n8k16 bf16 (HMMA, base PTX —
//              tcgen05 is rejected by the harness's sm_103 ptxas target).
//              Split-bf16 3-product accumulation for fp32-level accuracy.
//  lstm_persist: VERBATIM R11 (proven 7,970us).

#define T_STEPS 512
#define BATCH   128
#define HID     512
#define DIN     512
#define NG      2048
#define M_ALL   (T_STEPS * BATCH)
#define BH      (BATCH * HID)

__device__ float g_Gx[(size_t)M_ALL * NG];                 // 512 MB
__device__ __nv_bfloat16 g_Xhi[(size_t)M_ALL * DIN];       // 64 MB
__device__ __nv_bfloat16 g_Xlo[(size_t)M_ALL * DIN];       // 64 MB
__device__ __nv_bfloat16 g_Bhi[(size_t)NG * DIN];          // 2 MB  [gatecol][k]
__device__ __nv_bfloat16 g_Blo[(size_t)NG * DIN];          // 2 MB
__device__ float g_biasNG[NG];
__device__ unsigned int g_flag[4096];                      // flag[(ry*32+cx)*32]

typedef unsigned long long ull;
union F4U { float4 f; ull u[2]; float s[4]; };

__device__ __forceinline__ void ffma2(ull& d, ull a, ull b) {
    asm("fma.rn.f32x2 %0, %1, %2, %0;" : "+l"(d) : "l"(a), "l"(b));
}
__device__ __forceinline__ ull dup2(float x) {
    ull r; asm("mov.b64 %0, {%1, %1};" : "=l"(r) : "f"(x)); return r;
}
__device__ __forceinline__ void unpk(ull v, float& lo, float& hi) {
    asm("mov.b64 {%0, %1}, %2;" : "=f"(lo), "=f"(hi) : "l"(v));
}
__device__ __forceinline__ float sigm(float x) {
    return __fdividef(1.0f, 1.0f + __expf(-x));
}
__device__ __forceinline__ float tanh_(float x) {
    return __fdividef(2.0f, 1.0f + __expf(-2.0f * x)) - 1.0f;
}
__device__ __forceinline__ unsigned ld_acquire(const unsigned* p) {
    unsigned v;
    asm volatile("ld.acquire.gpu.global.u32 %0, [%1];" : "=r"(v) : "l"(p) : "memory");
    return v;
}
__device__ __forceinline__ void st_release(unsigned* p, unsigned v) {
    asm volatile("st.release.gpu.global.u32 [%0], %1;" :: "l"(p), "r"(v) : "memory");
}
__device__ __forceinline__ void barx(int id, int cnt) {
    asm volatile("bar.sync %0, %1;" :: "r"(id), "r"(cnt) : "memory");
}
__device__ __forceinline__ unsigned smem_u32(const void* p) {
    unsigned a;
    asm("{ .reg .u64 t; cvta.to.shared.u64 t, %1; cvt.u32.u64 %0, t; }" : "=r"(a) : "l"(p));
    return a;
}
__device__ __forceinline__ void ldx4(unsigned* r, unsigned addr) {
    asm volatile("ldmatrix.sync.aligned.m8n8.x4.shared.b16 {%0,%1,%2,%3}, [%4];"
                 : "=r"(r[0]), "=r"(r[1]), "=r"(r[2]), "=r"(r[3]) : "r"(addr));
}
__device__ __forceinline__ void mma16816(float* c, const unsigned* a,
                                         unsigned b0, unsigned b1) {
    asm volatile(
        "mma.sync.aligned.m16n8k16.row.col.f32.bf16.bf16.f32 "
        "{%0,%1,%2,%3}, {%4,%5,%6,%7}, {%8,%9}, {%0,%1,%2,%3};"
        : "+f"(c[0]), "+f"(c[1]), "+f"(c[2]), "+f"(c[3])
        : "r"(a[0]), "r"(a[1]), "r"(a[2]), "r"(a[3]), "r"(b0), "r"(b1));
}

// ---------------------------------------------------------------------------
// preconvert: split-bf16 X and gate-interleaved Wx; bias; flags.
// ---------------------------------------------------------------------------
#define XT  (M_ALL * DIN / 4)
#define BNW (NG * DIN)

__global__ __launch_bounds__(256) void preconvert(
    const float* __restrict__ X,
    const float* __restrict__ Wf, const float* __restrict__ Wi,
    const float* __restrict__ Wg, const float* __restrict__ Wo,
    const float* __restrict__ bfp, const float* __restrict__ bip,
    const float* __restrict__ bgp, const float* __restrict__ bop)
{
    long long n = (long long)blockIdx.x * 256 + threadIdx.x;
    if (n < XT) {
        long long i = n * 4;
        float4 x = *(const float4*)(X + i);
        float v[4] = {x.x, x.y, x.z, x.w};
        #pragma unroll
        for (int j = 0; j < 4; j++) {
            __nv_bfloat16 h = __float2bfloat16(v[j]);
            g_Xhi[i + j] = h;
            g_Xlo[i + j] = __float2bfloat16(v[j] - __bfloat162float(h));
        }
    } else if (n < XT + BNW) {
        long long m = n - XT;
        int grow = (int)(m / DIN);
        int k    = (int)(m % DIN);
        int unit = grow >> 2, gate = grow & 3;
        const float* W = (gate == 0) ? Wf : (gate == 1) ? Wi : (gate == 2) ? Wg : Wo;
        float w = W[(size_t)k * HID + unit];
        __nv_bfloat16 h = __float2bfloat16(w);
        g_Bhi[m] = h;
        g_Blo[m] = __float2bfloat16(w - __bfloat162float(h));
    } else if (n < XT + BNW + NG) {
        int col = (int)(n - XT - BNW);
        int unit = col >> 2, gate = col & 3;
        const float* b = (gate == 0) ? bfp : (gate == 1) ? bip : (gate == 2) ? bgp : bop;
        g_biasNG[col] = b[unit];
    } else if (n < XT + BNW + NG + 128) {
        int f = (int)(n - XT - BNW - NG);
        g_flag[f * 32] = 0;
    }
}

// ---------------------------------------------------------------------------
// tensor_gx: grid (16 n-tiles, 512 m-tiles), 256 thr = 8 warps (4m x 2n).
// CTA tile 128x128; warp tile 32x64; BK=32 smem slabs, 80B-padded rows.
// acc += Ahi*Bhi + Ahi*Blo + Alo*Bhi  (fp32 accumulate; lo*lo dropped).
// ---------------------------------------------------------------------------
#define SROW 40   // bf16 per smem row (80 bytes: conflict-free ldmatrix)

__global__ __launch_bounds__(256) void tensor_gx()
{
    __shared__ __align__(16) __nv_bfloat16 sAh[128 * SROW];
    __shared__ __align__(16) __nv_bfloat16 sAl[128 * SROW];
    __shared__ __align__(16) __nv_bfloat16 sBh[128 * SROW];
    __shared__ __align__(16) __nv_bfloat16 sBl[128 * SROW];

    const int tid  = threadIdx.x;
    const int wid  = tid >> 5;
    const int lane = tid & 31;
    const int wm   = wid >> 1;            // 0..3 -> m offset 32
    const int wn   = wid & 1;             // 0..1 -> n offset 64
    const int n0   = blockIdx.x * 128;
    const int m0   = blockIdx.y * 128;

    const unsigned uAh = smem_u32(sAh), uAl = smem_u32(sAl);
    const unsigned uBh = smem_u32(sBh), uBl = smem_u32(sBl);

    // ldmatrix lane-address offsets (bytes).
    const int agrp = lane >> 3;
    const unsigned aoffb = (unsigned)(((wm * 32 + (lane & 7) + (agrp & 1) * 8) * SROW
                                       + (agrp >> 1) * 8) * 2);
    const unsigned boffb = (unsigned)(((wn * 64 + (lane & 7) + ((agrp >> 1) & 1) * 8) * SROW
                                       + (agrp & 1) * 8) * 2);

    float acc[2][8][4];
    #pragma unroll
    for (int i = 0; i < 2; i++)
        #pragma unroll
        for (int j = 0; j < 8; j++)
            #pragma unroll
            for (int c = 0; c < 4; c++) acc[i][j][c] = 0.f;

    for (int ks = 0; ks < 16; ks++) {
        __syncthreads();
        const int kk = ks * 32;
        #pragma unroll
        for (int p = 0; p < 2; p++) {
            int cid = tid + p * 256;
            int row = cid >> 2, kc = cid & 3;
            size_t so = (size_t)(m0 + row) * DIN + kk + kc * 8;
            size_t bo = (size_t)(n0 + row) * DIN + kk + kc * 8;
            *(uint4*)(sAh + row * SROW + kc * 8) = *(const uint4*)(g_Xhi + so);
            *(uint4*)(sAl + row * SROW + kc * 8) = *(const uint4*)(g_Xlo + so);
            *(uint4*)(sBh + row * SROW + kc * 8) = *(const uint4*)(g_Bhi + bo);
            *(uint4*)(sBl + row * SROW + kc * 8) = *(const uint4*)(g_Blo + bo);
        }
        __syncthreads();

        #pragma unroll
        for (int k16 = 0; k16 < 2; k16++) {
            const unsigned kb = (unsigned)(k16 * 32);   // 16 bf16 = 32 bytes
            unsigned ah[2][4], al[2][4], bh[8][2], bl[8][2];
            #pragma unroll
            for (int i = 0; i < 2; i++) {
                ldx4(ah[i], uAh + aoffb + kb + i * 16 * (SROW * 2));
                ldx4(al[i], uAl + aoffb + kb + i * 16 * (SROW * 2));
            }
            #pragma unroll
            for (int p = 0; p < 4; p++) {
                unsigned r[4];
                ldx4(r, uBh + boffb + kb + p * 16 * (SROW * 2));
                bh[2*p][0] = r[0]; bh[2*p][1] = r[1];
                bh[2*p+1][0] = r[2]; bh[2*p+1][1] = r[3];
                ldx4(r, uBl + boffb + kb + p * 16 * (SROW * 2));
                bl[2*p][0] = r[0]; bl[2*p][1] = r[1];
                bl[2*p+1][0] = r[2]; bl[2*p+1][1] = r[3];
            }
            #pragma unroll
            for (int i = 0; i < 2; i++)
                #pragma unroll
                for (int j = 0; j < 8; j++) {
                    mma16816(acc[i][j], ah[i], bh[j][0], bh[j][1]);
                    mma16816(acc[i][j], ah[i], bl[j][0], bl[j][1]);
                    mma16816(acc[i][j], al[i], bh[j][0], bh[j][1]);
                }
        }
    }

    // Epilogue: + bias, write Gx. acc c0,c1 -> (row, col..col+1); c2,c3 -> row+8.
    const int rb = m0 + wm * 32 + (lane >> 2);
    const int cb = n0 + wn * 64 + (lane & 3) * 2;
    #pragma unroll
    for (int j = 0; j < 8; j++) {
        int col = cb + j * 8;
        float2 bb = *(const float2*)(g_biasNG + col);
        #pragma unroll
        for (int i = 0; i < 2; i++) {
            int r0 = rb + i * 16;
            float2 v0 = make_float2(acc[i][j][0] + bb.x, acc[i][j][1] + bb.y);
            float2 v1 = make_float2(acc[i][j][2] + bb.x, acc[i][j][3] + bb.y);
            __stcs((float2*)(g_Gx + (size_t)r0 * NG + col), v0);
            __stcs((float2*)(g_Gx + (size_t)(r0 + 8) * NG + col), v1);
        }
    }
}

// ---------------------------------------------------------------------------
// lstm_persist: VERBATIM R11 (7,970us). 128 CTAs x 256 thr, split-K 2 groups,
// per-producer dataflow flags, FFMA2 h-GEMM, fused epilogue split by group.
// ---------------------------------------------------------------------------
#define HSTRIDE 516
#define SMEM_PERSIST ((512 * 64 + 32 * HSTRIDE) * 4)

__global__ __launch_bounds__(256, 1) void lstm_persist(
    float* __restrict__ out, int write_final,
    const float* __restrict__ Wf, const float* __restrict__ Wi,
    const float* __restrict__ Wg, const float* __restrict__ Wo)
{
    extern __shared__ float smem[];
    float*  Ws  = smem;              // [512][64] gate-interleaved Wh slice
    float*  Hs  = smem + 512 * 64;   // [32][HSTRIDE] h staging
    float4* Cb  = (float4*)Hs;       // combine buffer overlay

    const int tid   = threadIdx.x;
    const int lane  = tid & 31;
    const int tg    = tid & 127;
    const int kg    = tid >> 7;
    const int tx    = tg & 15;
    const int ty    = tg >> 4;
    const int tx4   = tx << 2;
    const int cx    = blockIdx.x;
    const int col0  = cx * 64;
    const int ry    = blockIdx.y;
    const int row_base = ry * 32;
    const int j     = (col0 >> 2) + tx;
    const int r0    = row_base + ty * 4;
    const int kbase = kg * 256;
    const int io    = kg * 2;

    unsigned* fme = &g_flag[(ry * 32 + cx) * 32];
    const unsigned* fwatch = &g_flag[(ry * 32 + kg * 16 + (lane & 15)) * 32];

    {
        const int jbase = col0 >> 2;
        #pragma unroll
        for (int g = 0; g < 4; g++) {
            const float* Wp = (g == 0) ? Wf : (g == 1) ? Wi : (g == 2) ? Wg : Wo;
            for (int p = 0; p < 32; p++) {
                int idx = tid + p * 256;
                int k = idx >> 4, u = idx & 15;
                Ws[k * 64 + u * 4 + g] = Wp[(size_t)(DIN + k) * HID + jbase + u];
            }
        }
    }
    __syncthreads();

    float creg[2]  = {0.f, 0.f};
    float hlast[2] = {0.f, 0.f};

    const int frow = tg >> 2;
    const int fc4  = (tg & 3) << 2;

    const float* hrow[4];
    #pragma unroll
    for (int i = 0; i < 4; i++) hrow[i] = &Hs[(ty * 4 + i) * HSTRIDE + kbase];
    const float* wsp = Ws + (size_t)kbase * 64 + tx4;

    for (int t = 0; t < T_STEPS; t++) {
        float4 gx[2];
        {
            const float4* gxp = (const float4*)(g_Gx + ((size_t)t * BATCH + r0 + io) * NG + col0 + tx4);
            gx[0] = __ldcs(gxp);
            gx[1] = __ldcs(gxp + NG / 4);
        }

        ull acc[4][2];
        #pragma unroll
        for (int i = 0; i < 4; i++) { acc[i][0] = 0ull; acc[i][1] = 0ull; }

        if (t > 0) {
            while (ld_acquire(fwatch) < (unsigned)t) { }
            barx(1 + kg, 128);

            const float* hp = out + (size_t)(t - 1) * BH + (size_t)(row_base + frow) * HID;
            #pragma unroll
            for (int cc = 0; cc < 16; cc++) {
                int kc = (kg * 16 + cc) * 16 + fc4;
                float4 v = __ldcg((const float4*)(hp + kc));
                *(float4*)&Hs[frow * HSTRIDE + kc] = v;
            }
            barx(1 + kg, 128);

            F4U ha[4], wb[4], han[4], wbn[4];
            #pragma unroll
            for (int i = 0; i < 4; i++) ha[i].f = *(const float4*)(hrow[i]);
            #pragma unroll
            for (int kk = 0; kk < 4; kk++) wb[kk].f = *(const float4*)(wsp + kk * 64);

            #pragma unroll 2
            for (int g4 = 0; g4 < 64; g4++) {
                if (g4 < 63) {
                    int kn = (g4 + 1) * 4;
                    #pragma unroll
                    for (int i = 0; i < 4; i++) han[i].f = *(const float4*)(hrow[i] + kn);
                    #pragma unroll
                    for (int kk = 0; kk < 4; kk++) wbn[kk].f = *(const float4*)(wsp + (kn + kk) * 64);
                }
                #pragma unroll
                for (int kk = 0; kk < 4; kk++) {
                    ull w0 = wb[kk].u[0], w1 = wb[kk].u[1];
                    #pragma unroll
                    for (int i = 0; i < 4; i++) {
                        ull d = dup2(ha[i].s[kk]);
                        ffma2(acc[i][0], d, w0);
                        ffma2(acc[i][1], d, w1);
                    }
                }
                #pragma unroll
                for (int i = 0; i < 4; i++) ha[i] = han[i];
                #pragma unroll
                for (int kk = 0; kk < 4; kk++) wb[kk] = wbn[kk];
            }

            __syncthreads();
            {
                int iw0 = 2 - 2 * kg;
                #pragma unroll
                for (int ii = 0; ii < 2; ii++) {
                    int i = iw0 + ii;
                    F4U p; p.u[0] = acc[i][0]; p.u[1] = acc[i][1];
                    Cb[i * 128 + tg] = p.f;
                }
            }
            __syncthreads();
        }

        float* orow = out + (size_t)t * BH;
        #pragma unroll
        for (int ii = 0; ii < 2; ii++) {
            int i = io + ii;
            float pf, pi, pg, po;
            unpk(acc[i][0], pf, pi);
            unpk(acc[i][1], pg, po);
            if (t > 0) {
                F4U p; p.f = Cb[i * 128 + tg];
                pf += p.s[0]; pi += p.s[1]; pg += p.s[2]; po += p.s[3];
            }
            float f  = sigm(pf + gx[ii].x);
            float iv = sigm(pi + gx[ii].y);
            float g  = tanh_(pg + gx[ii].z);
            float o  = sigm(po + gx[ii].w);
            float cn = f * creg[ii] + iv * g;
            creg[ii] = cn;
            float h  = o * tanh_(cn);
            hlast[ii] = h;
            __stcg(&orow[(size_t)(r0 + i) * HID + j], h);
        }

        if (t < T_STEPS - 1) {
            __syncthreads();
            if (tid == 0) st_release(fme, (unsigned)(t + 1));
        }
    }

    if (write_final) {
        size_t base = (size_t)T_STEPS * BH;
        #pragma unroll
        for (int ii = 0; ii < 2; ii++) {
            out[base + (size_t)(r0 + io + ii) * HID + j]      = hlast[ii];
            out[base + BH + (size_t)(r0 + io + ii) * HID + j] = creg[ii];
        }
    }
}

// ---------------------------------------------------------------------------
extern "C" void kernel_launch(void* const* d_in, const int* in_sizes, int n_in,
                              void* d_out, int out_size)
{
    const float* x  = (const float*)d_in[0];
    const float* Wf = (const float*)d_in[1];
    const float* bf = (const float*)d_in[2];
    const float* Wi = (const float*)d_in[3];
    const float* bi = (const float*)d_in[4];
    const float* Wg = (const float*)d_in[5];
    const float* bg = (const float*)d_in[6];
    const float* Wo = (const float*)d_in[7];
    const float* bo = (const float*)d_in[8];
    float* out = (float*)d_out;

    static int attr_set = 0;
    if (!attr_set) {
        cudaFuncSetAttribute(lstm_persist,
                             cudaFuncAttributeMaxDynamicSharedMemorySize, SMEM_PERSIST);
        attr_set = 1;
    }

    long long total = (long long)XT + BNW + NG + 128;
    preconvert<<<(unsigned)((total + 255) / 256), 256>>>(x, Wf, Wi, Wg, Wo, bf, bi, bg, bo);

    tensor_gx<<<dim3(NG / 128, M_ALL / 128), 256>>>();

    long long need = (long long)T_STEPS * BH + 2LL * BH;
    int wf = ((long long)out_size >= need) ? 1 : 0;
    lstm_persist<<<dim3(32, 4), 256, SMEM_PERSIST>>>(out, wf, Wf, Wi, Wg, Wo);
}